// round 2
// baseline (speedup 1.0000x reference)
#include <cuda_runtime.h>
#include <cstdint>

// Problem constants
// I = 32, O = 16, K = 1 + 2*16 + 256 = 289, BATCH = 512
// out shape (B*K, 256) fp32; in shape (B, 1024) fp32.
// Projector tensor is one-hot/zero structured -> pure gather + zero-fill.

static constexpr int KPROJ = 289;
static constexpr int O2 = 256;           // O^2
static constexpr int I2 = 1024;          // I^2
static constexpr int F4_PER_BATCH = KPROJ * (O2 / 4);   // 289*64 = 18496

__global__ __launch_bounds__(256) void pooling_proj_kernel(
    const float* __restrict__ in,   // (512, 1024)
    float* __restrict__ out)        // (512, 289, 256)
{
    int tid = blockIdx.x * 256 + threadIdx.x;
    if (tid >= F4_PER_BATCH) return;
    int b  = blockIdx.y;

    int kk = tid >> 6;           // 0..288
    int o  = (tid & 63) << 2;    // 0..252, step 4

    const float* inb = in + (size_t)b * I2;
    float4 v = make_float4(0.f, 0.f, 0.f, 0.f);

    if (kk == 0) {
        // out[o+t] = in[(2i+1)*32 + 2j+1], i=o/16, j=(o+t)%16 (same i for t=0..3)
        int i = o >> 4, j = o & 15;
        int base = ((i << 1) + 1) * 32 + (j << 1) + 1;
        v.x = inb[base];
        v.y = inb[base + 2];
        v.z = inb[base + 4];
        v.w = inb[base + 6];
    } else if (kk <= 256) {
        int m = kk - 1;          // one-hot at o == m
        if ((m >> 2) == (o >> 2)) {
            int i = m >> 4, j = m & 15;
            float val = inb[(i << 6) + (j << 1)];   // 2*i*32 + 2*j
            switch (m & 3) {
                case 0: v.x = val; break;
                case 1: v.y = val; break;
                case 2: v.z = val; break;
                default: v.w = val; break;
            }
        }
    } else if (kk <= 272) {
        int i = kk - 257;        // nonzero where o>>4 == i
        if ((o >> 4) == i) {
            int j = o & 15;
            int base = (i << 6) + (j << 1) + 1;     // 2*i*32 + 2*j + 1
            v.x = inb[base];
            v.y = inb[base + 2];
            v.z = inb[base + 4];
            v.w = inb[base + 6];
        }
    } else {
        int j = kk - 273;        // nonzero where (o+t)&15 == j
        if ((j >> 2) == ((o & 15) >> 2)) {
            int i = o >> 4;
            float val = inb[((i << 1) + 1) * 32 + (j << 1)];
            switch (j & 3) {
                case 0: v.x = val; break;
                case 1: v.y = val; break;
                case 2: v.z = val; break;
                default: v.w = val; break;
            }
        }
    }

    float4* outp = reinterpret_cast<float4*>(
        out + ((size_t)b * KPROJ + kk) * O2 + o);
    *outp = v;
}

extern "C" void kernel_launch(void* const* d_in, const int* in_sizes, int n_in,
                              void* d_out, int out_size) {
    const float* input = (const float*)d_in[0];  // (512, 1024) fp32
    // d_in[1] = projectors — structurally known, never read.
    float* out = (float*)d_out;                  // 512*289*256 fp32

    dim3 grid((F4_PER_BATCH + 255) / 256, 512);  // (73, 512)
    pooling_proj_kernel<<<grid, 256>>>(input, out);
}

// round 4
// speedup vs baseline: 1.1405x; 1.1405x over previous
#include <cuda_runtime.h>
#include <cstdint>

// I = 32, O = 16, K = 1 + 2*16 + 256 = 289, BATCH = 512
// out (512, 289, 256) fp32 = 151.5 MB (must all be written: poisoned buffer);
// in (512, 1024) fp32 = 2 MB (L2-resident).
// Projector tensor is one-hot/zero structured -> pure gather + zero-fill.
// Pure store-bandwidth problem: batch-invariant offsets hoisted out of a
// 32-iteration batch loop for store ILP + long-lived blocks.

static constexpr int KPROJ = 289;
static constexpr int O2 = 256;                         // O^2
static constexpr int I2 = 1024;                        // I^2
static constexpr int BATCH = 512;
static constexpr int F4_PER_BATCH = KPROJ * (O2 / 4);  // 18496
static constexpr int GY = 16;                          // batch groups -> 32 iters/thread

__global__ __launch_bounds__(256) void pooling_proj_kernel(
    const float* __restrict__ in,   // (512, 1024)
    float* __restrict__ out)        // (512, 289, 256)
{
    int tid = blockIdx.x * 256 + threadIdx.x;
    if (tid >= F4_PER_BATCH) return;

    int kk = tid >> 6;           // 0..288
    int o  = (tid & 63) << 2;    // 0..252, step 4

    // Batch-invariant source offsets into a 1024-float input row.
    // offN < 0  ->  lane N writes 0.
    int off0 = -1, off1 = -1, off2 = -1, off3 = -1;

    if (kk == 0) {
        // src = (2i+1)*32 + 2j+1,  i=o>>4, j=(o+t)&15 (same i for t=0..3)
        int i = o >> 4, j = o & 15;
        int base = ((i << 1) + 1) * 32 + (j << 1) + 1;
        off0 = base; off1 = base + 2; off2 = base + 4; off3 = base + 6;
    } else if (kk <= 256) {
        // one-hot at o == m,  src = 2*(m>>4)*32 + 2*(m&15)
        int m = kk - 1;
        if ((m >> 2) == (o >> 2)) {
            int s = ((m >> 4) << 6) + ((m & 15) << 1);
            switch (m & 3) {
                case 0:  off0 = s; break;
                case 1:  off1 = s; break;
                case 2:  off2 = s; break;
                default: off3 = s; break;
            }
        }
    } else if (kk <= 272) {
        // nonzero where o>>4 == i,  src = 2i*32 + 2j+1
        int i = kk - 257;
        if ((o >> 4) == i) {
            int base = (i << 6) + ((o & 15) << 1) + 1;
            off0 = base; off1 = base + 2; off2 = base + 4; off3 = base + 6;
        }
    } else {
        // nonzero where (o+t)&15 == j,  src = (2i+1)*32 + 2j
        int j = kk - 273;
        if ((j >> 2) == ((o & 15) >> 2)) {
            int s = (((o >> 4) << 1) + 1) * 32 + (j << 1);
            switch (j & 3) {
                case 0:  off0 = s; break;
                case 1:  off1 = s; break;
                case 2:  off2 = s; break;
                default: off3 = s; break;
            }
        }
    }

    const float* inp  = in  + (size_t)blockIdx.y * I2;
    float*       outp = out + ((size_t)blockIdx.y * KPROJ + kk) * O2 + o;
    const size_t in_stride  = (size_t)GY * I2;
    const size_t out_stride = (size_t)GY * KPROJ * O2;

    #pragma unroll 4
    for (int b = blockIdx.y; b < BATCH; b += GY) {
        float4 v = make_float4(0.f, 0.f, 0.f, 0.f);
        if (off0 >= 0) v.x = __ldg(inp + off0);
        if (off1 >= 0) v.y = __ldg(inp + off1);
        if (off2 >= 0) v.z = __ldg(inp + off2);
        if (off3 >= 0) v.w = __ldg(inp + off3);
        __stcs(reinterpret_cast<float4*>(outp), v);
        inp  += in_stride;
        outp += out_stride;
    }
}

extern "C" void kernel_launch(void* const* d_in, const int* in_sizes, int n_in,
                              void* d_out, int out_size) {
    const float* input = (const float*)d_in[0];  // (512, 1024) fp32
    // d_in[1] = projectors — structurally known, never read.
    float* out = (float*)d_out;                  // 512*289*256 fp32

    dim3 grid((F4_PER_BATCH + 255) / 256, GY);   // (73, 16) = 1168 blocks
    pooling_proj_kernel<<<grid, 256>>>(input, out);
}